// round 2
// baseline (speedup 1.0000x reference)
#include <cuda_runtime.h>
#include <math.h>

// ---------------- scratch (device globals, no allocation) ----------------
__device__ float g_feats[8192 * 8];
__device__ float g_Ur[256 * 256];
__device__ float g_Ui[256 * 256];
__device__ float g_M[256 * 256];
__device__ float g_T[6561];

// ---------------- complex helpers ----------------
__device__ __forceinline__ float2 cmul(float2 a, float2 b) {
    return make_float2(a.x * b.x - a.y * b.y, a.x * b.y + a.y * b.x);
}
__device__ __forceinline__ float2 cadd(float2 a, float2 b) {
    return make_float2(a.x + b.x, a.y + b.y);
}

// Pauli matrices I,X,Y,Z
__constant__ float2 c_P[4][2][2] = {
    { { {1.f,0.f},{0.f,0.f} }, { {0.f,0.f},{1.f,0.f} } },   // I
    { { {0.f,0.f},{1.f,0.f} }, { {1.f,0.f},{0.f,0.f} } },   // X
    { { {0.f,0.f},{0.f,-1.f} }, { {0.f,1.f},{0.f,0.f} } },  // Y
    { { {1.f,0.f},{0.f,0.f} }, { {0.f,0.f},{-1.f,0.f} } },  // Z
};

// ---------------- K1: feats = tanh(x @ fc_w^T + fc_b) ----------------
// grid 256 x 256 threads. warp handles 4 rows; fc_w (8x3072) staged in smem.
__global__ __launch_bounds__(256) void feats_kernel(const float* __restrict__ x,
                                                    const float* __restrict__ fcw,
                                                    const float* __restrict__ fcb) {
    extern __shared__ float wsh[];  // 8*3072 floats = 96KB
    int tid = threadIdx.x;
    for (int i = tid * 4; i < 8 * 3072; i += 256 * 4)
        *(float4*)&wsh[i] = *(const float4*)&fcw[i];
    __syncthreads();

    int warp = tid >> 5, lane = tid & 31;
    int grp = blockIdx.x * 8 + warp;      // 0..2047
    long long row0 = (long long)grp * 4;  // 4 rows per warp

    float acc[8][4];
#pragma unroll
    for (int q = 0; q < 8; q++)
#pragma unroll
        for (int r = 0; r < 4; r++) acc[q][r] = 0.f;

#pragma unroll 4
    for (int it = 0; it < 24; it++) {
        int c = (it * 32 + lane) * 4;
        float4 xv[4];
#pragma unroll
        for (int r = 0; r < 4; r++)
            xv[r] = *(const float4*)&x[(row0 + r) * 3072 + c];
#pragma unroll
        for (int q = 0; q < 8; q++) {
            float4 wv = *(const float4*)&wsh[q * 3072 + c];
#pragma unroll
            for (int r = 0; r < 4; r++) {
                acc[q][r] += wv.x * xv[r].x + wv.y * xv[r].y +
                             wv.z * xv[r].z + wv.w * xv[r].w;
            }
        }
    }
#pragma unroll
    for (int q = 0; q < 8; q++) {
#pragma unroll
        for (int r = 0; r < 4; r++) {
            float v = acc[q][r];
            v += __shfl_down_sync(0xffffffffu, v, 16);
            v += __shfl_down_sync(0xffffffffu, v, 8);
            v += __shfl_down_sync(0xffffffffu, v, 4);
            v += __shfl_down_sync(0xffffffffu, v, 2);
            v += __shfl_down_sync(0xffffffffu, v, 1);
            if (lane == 0) g_feats[(row0 + r) * 8 + q] = tanhf(v + fcb[q]);
        }
    }
}

// ---------------- K2: simulate fixed circuit, produce U columns ----------------
__device__ __forceinline__ void u3g(float th, float ph, float dl, float2 g[2][2]) {
    float st, ct; __sincosf(0.5f * th, &st, &ct);
    float sp, cp; __sincosf(ph, &sp, &cp);
    float sd, cd; __sincosf(dl, &sd, &cd);
    float spd, cpd; __sincosf(ph + dl, &spd, &cpd);
    g[0][0] = make_float2(ct, 0.f);
    g[0][1] = make_float2(-cd * st, -sd * st);
    g[1][0] = make_float2(cp * st, sp * st);
    g[1][1] = make_float2(cpd * ct, spd * ct);
}

__device__ __forceinline__ void zero4(float2 g[4][4]) {
#pragma unroll
    for (int r = 0; r < 4; r++)
#pragma unroll
        for (int c = 0; c < 4; c++) g[r][c] = make_float2(0.f, 0.f);
}

__device__ __forceinline__ void apply1(float2* s, const float2 g[2][2], int w, int t) {
    __syncthreads();
    int m = 1 << (7 - w);
#pragma unroll
    for (int r = 0; r < 2; r++) {
        int pi = t + 64 * r;
        int k0 = ((pi & ~(m - 1)) << 1) | (pi & (m - 1));
        int k1 = k0 | m;
        float2 a = s[k0], b = s[k1];
        s[k0] = cadd(cmul(g[0][0], a), cmul(g[0][1], b));
        s[k1] = cadd(cmul(g[1][0], a), cmul(g[1][1], b));
    }
}

__device__ __forceinline__ void apply2(float2* s, const float2 g[4][4], int wa, int wb, int t) {
    __syncthreads();
    int ma = 1 << (7 - wa), mb = 1 << (7 - wb);
    int lo = ma < mb ? ma : mb;
    int hi = ma < mb ? mb : ma;
    int k = t;
    k = ((k & ~(lo - 1)) << 1) | (k & (lo - 1));
    k = ((k & ~(hi - 1)) << 1) | (k & (hi - 1));
    int i0 = k, i1 = k | mb, i2 = k | ma, i3 = k | ma | mb;
    float2 v0 = s[i0], v1 = s[i1], v2 = s[i2], v3 = s[i3];
    float2 o0 = cadd(cadd(cmul(g[0][0], v0), cmul(g[0][1], v1)),
                     cadd(cmul(g[0][2], v2), cmul(g[0][3], v3)));
    float2 o1 = cadd(cadd(cmul(g[1][0], v0), cmul(g[1][1], v1)),
                     cadd(cmul(g[1][2], v2), cmul(g[1][3], v3)));
    float2 o2 = cadd(cadd(cmul(g[2][0], v0), cmul(g[2][1], v1)),
                     cadd(cmul(g[2][2], v2), cmul(g[2][3], v3)));
    float2 o3 = cadd(cadd(cmul(g[3][0], v0), cmul(g[3][1], v1)),
                     cadd(cmul(g[3][2], v2), cmul(g[3][3], v3)));
    s[i0] = o0; s[i1] = o1; s[i2] = o2; s[i3] = o3;
}

__device__ __forceinline__ void conv_pair(float2* s, const float* cw, int idx,
                                          int a, int b, int t) {
    float2 g2[2][2];
    float2 g4[4][4];
    u3g(cw[idx * 15 + 0], cw[idx * 15 + 1], cw[idx * 15 + 2], g2);
    apply1(s, g2, a, t);
    u3g(cw[(idx + 1) * 15 + 3], cw[(idx + 1) * 15 + 4], cw[(idx + 1) * 15 + 5], g2);
    apply1(s, g2, b, t);
    // ZZ
    {
        float sn, cs; __sincosf(0.5f * cw[idx * 15 + 6], &sn, &cs);
        zero4(g4);
        g4[0][0] = make_float2(cs, -sn);
        g4[1][1] = make_float2(cs, sn);
        g4[2][2] = make_float2(cs, sn);
        g4[3][3] = make_float2(cs, -sn);
        apply2(s, g4, a, b, t);
    }
    // YY
    {
        float sn, cs; __sincosf(0.5f * cw[idx * 15 + 7], &sn, &cs);
        zero4(g4);
        g4[0][0] = g4[1][1] = g4[2][2] = g4[3][3] = make_float2(cs, 0.f);
        g4[0][3] = make_float2(0.f, sn);
        g4[1][2] = make_float2(0.f, -sn);
        g4[2][1] = make_float2(0.f, -sn);
        g4[3][0] = make_float2(0.f, sn);
        apply2(s, g4, a, b, t);
    }
    // XX
    {
        float sn, cs; __sincosf(0.5f * cw[idx * 15 + 8], &sn, &cs);
        zero4(g4);
        g4[0][0] = g4[1][1] = g4[2][2] = g4[3][3] = make_float2(cs, 0.f);
        g4[0][3] = g4[1][2] = g4[2][1] = g4[3][0] = make_float2(0.f, -sn);
        apply2(s, g4, a, b, t);
    }
    u3g(cw[idx * 15 + 9], cw[idx * 15 + 10], cw[idx * 15 + 11], g2);
    apply1(s, g2, a, t);
    u3g(cw[(idx + 1) * 15 + 12], cw[(idx + 1) * 15 + 13], cw[(idx + 1) * 15 + 14], g2);
    apply1(s, g2, b, t);
}

__global__ __launch_bounds__(64) void circuit_kernel(const float* __restrict__ conv,
                                                     const float* __restrict__ pool,
                                                     const float* __restrict__ last) {
    __shared__ float2 s[256];
    int t = threadIdx.x;
    int col = blockIdx.x;
    for (int k = t; k < 256; k += 64)
        s[k] = make_float2(k == col ? 1.f : 0.f, 0.f);

    int wires[8] = {0, 1, 2, 3, 4, 5, 6, 7};
    int nw = 8;
    for (int layer = 0; layer < 2; layer++) {
        const float* cw = conv + layer * 8 * 15;
        for (int p = 0; p < 2; p++)
            for (int idx = 0; idx < nw - 1; idx++)
                if ((idx & 1) == p)
                    conv_pair(s, cw, idx, wires[idx], wires[idx + 1], t);
        const float* pw = pool + layer * 4 * 3;
        for (int idx = 1; idx < nw; idx += 2) {
            float2 u[2][2];
            u3g(pw[(idx >> 1) * 3 + 0], pw[(idx >> 1) * 3 + 1], pw[(idx >> 1) * 3 + 2], u);
            float2 g4[4][4];
            zero4(g4);
            g4[0][0] = make_float2(1.f, 0.f);
            g4[1][1] = make_float2(1.f, 0.f);
            g4[2][2] = u[0][0]; g4[2][3] = u[0][1];
            g4[3][2] = u[1][0]; g4[3][3] = u[1][1];
            apply2(s, g4, wires[idx], wires[idx - 1], t);  // control = wires[idx]
        }
        for (int i = 0; i < nw / 2; i++) wires[i] = wires[2 * i];
        nw >>= 1;
    }
    // last 15 Pauli-word gates on (wires[0], wires[1]) = (0, 4)
    for (int kk = 0; kk < 15; kk++) {
        int pa = (kk + 1) >> 2, pb = (kk + 1) & 3;
        float sn, cs; __sincosf(0.5f * last[kk], &sn, &cs);
        float2 g4[4][4];
#pragma unroll
        for (int r = 0; r < 4; r++)
#pragma unroll
            for (int c = 0; c < 4; c++) {
                float2 p2 = cmul(c_P[pa][r >> 1][c >> 1], c_P[pb][r & 1][c & 1]);
                // cs*I - i*sn*P2
                g4[r][c] = make_float2((r == c ? cs : 0.f) + sn * p2.y, -sn * p2.x);
            }
        apply2(s, g4, wires[0], wires[1], t);
    }
    __syncthreads();
    for (int k = t; k < 256; k += 64) {
        g_Ur[k * 256 + col] = s[k].x;
        g_Ui[k * 256 + col] = s[k].y;
    }
}

// ---------------- K3: M = Ur^T diag(z) Ur + Ui^T diag(z) Ui ----------------
__global__ __launch_bounds__(256) void msyrk_kernel() {
    int bi = blockIdx.y * 16, bj = blockIdx.x * 16;
    int tx = threadIdx.x & 15, ty = threadIdx.x >> 4;
    __shared__ float Air[16][17], Aii[16][17], Ajr[16][17], Aji[16][17];
    float acc = 0.f;
    for (int k0 = 0; k0 < 256; k0 += 16) {
        int k = k0 + ty;
        float z = (k & 128) ? -1.f : 1.f;  // wire 0 is the MSB
        Air[ty][tx] = z * g_Ur[k * 256 + bi + tx];
        Aii[ty][tx] = z * g_Ui[k * 256 + bi + tx];
        Ajr[ty][tx] = g_Ur[k * 256 + bj + tx];
        Aji[ty][tx] = g_Ui[k * 256 + bj + tx];
        __syncthreads();
#pragma unroll
        for (int kkk = 0; kkk < 16; kkk++)
            acc += Air[kkk][ty] * Ajr[kkk][tx] + Aii[kkk][ty] * Aji[kkk][tx];
        __syncthreads();
    }
    g_M[(bi + ty) * 256 + bj + tx] = acc;
}

// ---------------- K4: M -> T (Pauli coefficients over {I,Z,X}^8) ----------------
// 81 blocks; block b fixes digits (p0..p3), contracts wires 0..3 from M, then
// contracts wires 7,6,5,4 freely -> T[b*81 + (p4*27+p5*9+p6*3+p7)].
__global__ __launch_bounds__(256) void pauli_kernel() {
    extern __shared__ float sm[];
    float* A = sm;           // 16384 floats
    float* B = sm + 16384;   // 4096 floats
    int t = threadIdx.x;
    int b = blockIdx.x;
    int pd[4];
    pd[0] = b / 27; pd[1] = (b / 9) % 3; pd[2] = (b / 3) % 3; pd[3] = b % 3;

    // stage 0: M (dim 256) -> A (128x128), digit p0
    {
        int p = pd[0];
        for (int o = t; o < 128 * 128; o += 256) {
            int i = o >> 7, j = o & 127;
            float v;
            if (p == 0)      v = g_M[i * 256 + j] + g_M[(i + 128) * 256 + j + 128];
            else if (p == 1) v = g_M[i * 256 + j] - g_M[(i + 128) * 256 + j + 128];
            else             v = g_M[i * 256 + j + 128] + g_M[(i + 128) * 256 + j];
            A[o] = v;
        }
    }
    __syncthreads();
    // stage 1: A (128) -> B (64x64), digit p1
    {
        int p = pd[1];
        for (int o = t; o < 64 * 64; o += 256) {
            int i = o >> 6, j = o & 63;
            float v;
            if (p == 0)      v = A[i * 128 + j] + A[(i + 64) * 128 + j + 64];
            else if (p == 1) v = A[i * 128 + j] - A[(i + 64) * 128 + j + 64];
            else             v = A[i * 128 + j + 64] + A[(i + 64) * 128 + j];
            B[o] = v;
        }
    }
    __syncthreads();
    // stage 2: B (64) -> A (32x32), digit p2
    {
        int p = pd[2];
        for (int o = t; o < 32 * 32; o += 256) {
            int i = o >> 5, j = o & 31;
            float v;
            if (p == 0)      v = B[i * 64 + j] + B[(i + 32) * 64 + j + 32];
            else if (p == 1) v = B[i * 64 + j] - B[(i + 32) * 64 + j + 32];
            else             v = B[i * 64 + j + 32] + B[(i + 32) * 64 + j];
            A[o] = v;
        }
    }
    __syncthreads();
    // stage 3: A (32) -> B (16x16), digit p3
    {
        int p = pd[3];
        for (int o = t; o < 16 * 16; o += 256) {
            int i = o >> 4, j = o & 15;
            float v;
            if (p == 0)      v = A[i * 32 + j] + A[(i + 16) * 32 + j + 16];
            else if (p == 1) v = A[i * 32 + j] - A[(i + 16) * 32 + j + 16];
            else             v = A[i * 32 + j + 16] + A[(i + 16) * 32 + j];
            B[o] = v;
        }
    }
    __syncthreads();
    // stage 4: contract wire 7 (LSB). B [16][16] -> A [(i*8+j)*3 + p7], 192 entries
    for (int o = t; o < 192; o += 256) {
        int p = o % 3, rest = o / 3;
        int i = rest >> 3, j = rest & 7;
        float a00 = B[(2 * i) * 16 + 2 * j],     a11 = B[(2 * i + 1) * 16 + 2 * j + 1];
        float a01 = B[(2 * i) * 16 + 2 * j + 1], a10 = B[(2 * i + 1) * 16 + 2 * j];
        A[o] = (p == 0) ? (a00 + a11) : (p == 1) ? (a00 - a11) : (a01 + a10);
    }
    __syncthreads();
    // stage 5: contract wire 6. A [(i*8+j)*3+r] -> B [(i*4+j)*9 + p*3 + r], 144
    for (int o = t; o < 144; o += 256) {
        int r2 = o % 9, rest = o / 9;
        int p = r2 / 3, r = r2 % 3;
        int i = rest >> 2, j = rest & 3;
        float a00 = A[((2 * i) * 8 + 2 * j) * 3 + r],     a11 = A[((2 * i + 1) * 8 + 2 * j + 1) * 3 + r];
        float a01 = A[((2 * i) * 8 + 2 * j + 1) * 3 + r], a10 = A[((2 * i + 1) * 8 + 2 * j) * 3 + r];
        B[o] = (p == 0) ? (a00 + a11) : (p == 1) ? (a00 - a11) : (a01 + a10);
    }
    __syncthreads();
    // stage 6: contract wire 5. B [(i*4+j)*9+r] -> A [(i*2+j)*27 + p*9 + r], 108
    for (int o = t; o < 108; o += 256) {
        int r2 = o % 27, rest = o / 27;
        int p = r2 / 9, r = r2 % 9;
        int i = rest >> 1, j = rest & 1;
        float a00 = B[((2 * i) * 4 + 2 * j) * 9 + r],     a11 = B[((2 * i + 1) * 4 + 2 * j + 1) * 9 + r];
        float a01 = B[((2 * i) * 4 + 2 * j + 1) * 9 + r], a10 = B[((2 * i + 1) * 4 + 2 * j) * 9 + r];
        A[o] = (p == 0) ? (a00 + a11) : (p == 1) ? (a00 - a11) : (a01 + a10);
    }
    __syncthreads();
    // stage 7: contract wire 4. A [(i*2+j)*27+r] -> T[b*81 + p*27 + r], 81
    for (int o = t; o < 81; o += 256) {
        int p = o / 27, r = o % 27;
        float a00 = A[0 * 27 + r], a11 = A[3 * 27 + r];
        float a01 = A[1 * 27 + r], a10 = A[2 * 27 + r];
        g_T[b * 81 + o] = (p == 0) ? (a00 + a11) : (p == 1) ? (a00 - a11) : (a01 + a10);
    }
}

// ---------------- K5: per-sample qval = a^T T b / 256; logits ----------------
__device__ __forceinline__ float selt(int d, float c, float s) {
    return d == 0 ? 1.f : (d == 1 ? c : s);
}

__global__ __launch_bounds__(256) void logits_kernel(const float* __restrict__ out_w,
                                                     const float* __restrict__ out_b,
                                                     float* __restrict__ out) {
    __shared__ __align__(16) float Tsh[81 * 84];
    __shared__ __align__(16) float bsh[8][84];
    int tid = threadIdx.x;
    for (int i = tid; i < 81 * 84; i += 256) Tsh[i] = 0.f;
    for (int i = tid; i < 8 * 84; i += 256) ((float*)bsh)[i] = 0.f;
    __syncthreads();
    for (int i = tid; i < 6561; i += 256)
        Tsh[(i / 81) * 84 + (i % 81)] = g_T[i];
    __syncthreads();

    int warp = tid >> 5, lane = tid & 31;
    float ow = (lane < 10) ? out_w[lane] : 0.f;
    float ob = (lane < 10) ? out_b[lane] : 0.f;

    for (int rnd = 0; rnd < 8; rnd++) {
        int s = blockIdx.x * 64 + warp * 8 + rnd;
        float tc[8], ts[8];
#pragma unroll
        for (int w = 0; w < 8; w++) {
            float f = g_feats[s * 8 + w];
            __sincosf(f, &ts[w], &tc[w]);
        }
        __syncwarp();
        for (int n = lane; n < 81; n += 32) {
            int d4 = n / 27, d5 = (n / 9) % 3, d6 = (n / 3) % 3, d7 = n % 3;
            bsh[warp][n] = selt(d4, tc[4], ts[4]) * selt(d5, tc[5], ts[5]) *
                           selt(d6, tc[6], ts[6]) * selt(d7, tc[7], ts[7]);
        }
        __syncwarp();
        float acc = 0.f;
        for (int m = lane; m < 81; m += 32) {
            float am = selt(m / 27, tc[0], ts[0]) * selt((m / 9) % 3, tc[1], ts[1]) *
                       selt((m / 3) % 3, tc[2], ts[2]) * selt(m % 3, tc[3], ts[3]);
            float rs = 0.f;
#pragma unroll
            for (int n4 = 0; n4 < 21; n4++) {
                float4 tv = *(const float4*)&Tsh[m * 84 + n4 * 4];
                float4 bv = *(const float4*)&bsh[warp][n4 * 4];
                rs += tv.x * bv.x + tv.y * bv.y + tv.z * bv.z + tv.w * bv.w;
            }
            acc += am * rs;
        }
        acc += __shfl_down_sync(0xffffffffu, acc, 16);
        acc += __shfl_down_sync(0xffffffffu, acc, 8);
        acc += __shfl_down_sync(0xffffffffu, acc, 4);
        acc += __shfl_down_sync(0xffffffffu, acc, 2);
        acc += __shfl_down_sync(0xffffffffu, acc, 1);
        float qv = __shfl_sync(0xffffffffu, acc, 0) * (1.0f / 256.0f);
        if (lane < 10) out[s * 10 + lane] = qv * ow + ob;
        __syncwarp();
    }
}

// ---------------- launch ----------------
extern "C" void kernel_launch(void* const* d_in, const int* in_sizes, int n_in,
                              void* d_out, int out_size) {
    const float* x     = (const float*)d_in[0];
    const float* fcw   = (const float*)d_in[1];
    const float* fcb   = (const float*)d_in[2];
    const float* conv  = (const float*)d_in[3];
    const float* pool  = (const float*)d_in[4];
    const float* last  = (const float*)d_in[5];
    const float* out_w = (const float*)d_in[6];
    const float* out_b = (const float*)d_in[7];
    float* out = (float*)d_out;

    cudaFuncSetAttribute(feats_kernel, cudaFuncAttributeMaxDynamicSharedMemorySize, 8 * 3072 * 4);
    cudaFuncSetAttribute(pauli_kernel, cudaFuncAttributeMaxDynamicSharedMemorySize, 20480 * 4);

    feats_kernel<<<256, 256, 8 * 3072 * 4>>>(x, fcw, fcb);
    circuit_kernel<<<256, 64>>>(conv, pool, last);
    msyrk_kernel<<<dim3(16, 16), 256>>>();
    pauli_kernel<<<81, 256, 20480 * 4>>>();
    logits_kernel<<<128, 256>>>(out_w, out_b, out);
}